// round 6
// baseline (speedup 1.0000x reference)
#include <cuda_runtime.h>
#include <cuda_bf16.h>
#include <cstdint>

// SINSentAddEmb: out[b,n,:] = LayerNorm(pe[n] + pe[para[b,n]] + pe[sent[b,n]]) * gamma + beta
// top_vecs (d_in[0]) is unused by the reference math — never read it.
//
// R5: kernel is L2-request-CONCURRENCY bound (achieved LTS BW tracks per-warp LDG
// depth, not occupancy, not capacity). Stage the two gathered pe rows via cp.async
// (LDGSTS: no destination registers, no consumer stalls) into smem, keeping the
// R4 traffic reduction (pe[n] staged once per block). Values are read from smem
// twice (sum pass + normalize pass); nothing row-sized lives in registers.
//
// Fixed shape: B=8, N=4096, H=1024, MAX_NSENT=5000, EPS=1e-12.
// sent_struct_vec is int32 on device (JAX downcasts int64 with x64 off).

#define HDIM   1024
#define H4     (HDIM / 4)      // 256 float4 per row
#define NPOS   4096
#define NBATCH 8
#define RPB    4               // rows (batches) per block -> 128-thread blocks
#define EPS_LN 1e-12f

__device__ __forceinline__ void cp_async16(void* smem_dst, const void* gmem_src) {
    unsigned s = (unsigned)__cvta_generic_to_shared(smem_dst);
    asm volatile("cp.async.cg.shared.global [%0], [%1], 16;\n" :: "r"(s), "l"(gmem_src));
}

__global__ __launch_bounds__(RPB * 32)
void sinsent_addemb_ln_kernel(const int2*   __restrict__ ssv2,    // (B*N) int32 pairs (para, sent)
                              const float4* __restrict__ pe4,     // (MAX_NSENT, H/4)
                              const float4* __restrict__ gamma4,  // (H/4)
                              const float4* __restrict__ beta4,   // (H/4)
                              float4*       __restrict__ out4)    // (B*N, H/4)
{
    __shared__ float4 spe[H4];                // pe[n], 4 KB
    __shared__ float4 srow[RPB][2][H4];       // per-row staged pe[para], pe[sent], 32 KB

    const int n    = blockIdx.x >> 1;         // sequence position
    const int half = blockIdx.x & 1;          // which 4 batches
    const int w    = threadIdx.x >> 5;        // warp -> row within block
    const int lane = threadIdx.x & 31;
    const int b    = half * RPB + w;          // batch index
    const int row  = b * NPOS + n;            // output row (b, n)

    // Indices for this warp's row (uniform -> broadcast).
    const int2 idx = ssv2[row];
    const float4* __restrict__ pp = pe4 + (size_t)idx.x * H4;
    const float4* __restrict__ ps = pe4 + (size_t)idx.y * H4;
    const float4* __restrict__ pn = pe4 + (size_t)n     * H4;

    // Async stage pe[n] (whole block: 128 threads x 2 float4 = 4 KB).
    cp_async16(&spe[threadIdx.x],       &pn[threadIdx.x]);
    cp_async16(&spe[threadIdx.x + 128], &pn[threadIdx.x + 128]);

    // Async stage this warp's two gathered rows: 16 independent 16B copies per lane,
    // no destination registers -> deep, stall-free L2 request stream.
#pragma unroll
    for (int k = 0; k < 8; k++) {
        const int j = k * 32 + lane;
        cp_async16(&srow[w][0][j], &pp[j]);
        cp_async16(&srow[w][1][j], &ps[j]);
    }
    asm volatile("cp.async.commit_group;\n" ::: "memory");
    asm volatile("cp.async.wait_group 0;\n" ::: "memory");
    __syncthreads();                          // spe written by other warps

    // Pass 1: sum / sumsq from smem (conflict-free: consecutive lanes, consecutive float4).
    float s = 0.0f, sq = 0.0f;
#pragma unroll
    for (int k = 0; k < 8; k++) {
        const int j = k * 32 + lane;
        const float4 a  = spe[j];
        const float4 bb = srow[w][0][j];
        const float4 c  = srow[w][1][j];
        const float vx = a.x + bb.x + c.x;
        const float vy = a.y + bb.y + c.y;
        const float vz = a.z + bb.z + c.z;
        const float vw = a.w + bb.w + c.w;
        s  += vx + vy + vz + vw;
        sq += vx * vx + vy * vy + vz * vz + vw * vw;
    }

#pragma unroll
    for (int o = 16; o > 0; o >>= 1) {
        s  += __shfl_xor_sync(0xffffffffu, s,  o);
        sq += __shfl_xor_sync(0xffffffffu, sq, o);
    }

    const float mean = s  * (1.0f / HDIM);
    const float var  = sq * (1.0f / HDIM) - mean * mean;
    const float rstd = rsqrtf(var + EPS_LN);

    // Pass 2: recompute v from smem, scale, store.
    float4* __restrict__ orow = out4 + (size_t)row * H4;
#pragma unroll
    for (int k = 0; k < 8; k++) {
        const int j = k * 32 + lane;
        const float4 a  = spe[j];
        const float4 bb = srow[w][0][j];
        const float4 c  = srow[w][1][j];
        const float4 g  = gamma4[j];          // L1-resident (8 KB total)
        const float4 bt = beta4[j];
        float4 o;
        o.x = (a.x + bb.x + c.x - mean) * rstd * g.x + bt.x;
        o.y = (a.y + bb.y + c.y - mean) * rstd * g.y + bt.y;
        o.z = (a.z + bb.z + c.z - mean) * rstd * g.z + bt.z;
        o.w = (a.w + bb.w + c.w - mean) * rstd * g.w + bt.w;
        orow[j] = o;                          // STG.128, fully coalesced
    }
}

extern "C" void kernel_launch(void* const* d_in, const int* in_sizes, int n_in,
                              void* d_out, int out_size)
{
    // metadata order: [0] top_vecs f32 (UNUSED), [1] sent_struct_vec int32,
    //                 [2] pe f32, [3] gamma f32, [4] beta f32
    const int2*   ssv2   = (const int2*)d_in[1];
    const float4* pe4    = (const float4*)d_in[2];
    const float4* gamma4 = (const float4*)d_in[3];
    const float4* beta4  = (const float4*)d_in[4];
    float4*       out4   = (float4*)d_out;

    const int blocks = NPOS * (NBATCH / RPB); // 8192
    sinsent_addemb_ln_kernel<<<blocks, RPB * 32>>>(ssv2, pe4, gamma4, beta4, out4);
}